// round 9
// baseline (speedup 1.0000x reference)
#include <cuda_runtime.h>
#include <cstdint>
#include <math.h>

#define BATCH 8
#define NA 131072            // anchors per batch (2^17)
#define NPRE 6000            // PRE_NMS_LIMIT
#define NB 94                // ceil(NPRE/64)  (fallback mask words/row)
#define NPROP 1000
#define CAND_CAP 8192
#define HBINS 16384          // key >> 18
#define NMS_THR 0.7f
#define N1 1536              // fast-path prefix rows
#define ECAP 6144            // edge list capacity per batch
#define PASSMAX 64
#define NBLK 148
#define NTHR 256
#define SMEM_BYTES 73728     // ping 4*1536*8 + pong 2*1536*8

typedef unsigned long long u64;

// ---------------- device scratch (static, no allocation) ----------------
// Invariants: g_hist all-zero, g_cand_cnt/g_ecnt zero at entry (zero-init at
// load; each consuming phase re-zeroes after use).
__device__ unsigned int  g_hist[BATCH * HBINS];
__device__ int           g_cutbin[BATCH];
__device__ int           g_cand_cnt[BATCH];
__device__ u64           g_cand[BATCH * CAND_CAP];
__device__ float4        g_boxes[BATCH * NPRE];
__device__ int           g_ecnt[BATCH];
__device__ unsigned int  g_edges[BATCH * ECAP];
__device__ u64           g_mask[(size_t)BATCH * NPRE * NB];   // also merge scratch
__device__ unsigned char g_keep[BATCH * NPRE];
__device__ int           g_done[BATCH];
__device__ int           g_bar_count;
__device__ volatile int  g_bar_gen;

// ---------------- helpers ----------------
static __device__ __forceinline__ void grid_barrier() {
    __syncthreads();
    if (threadIdx.x == 0) {
        __threadfence();
        int gen = g_bar_gen;
        if (atomicAdd(&g_bar_count, 1) == NBLK - 1) {
            g_bar_count = 0;
            __threadfence();
            g_bar_gen = gen + 1;
        } else {
            while (g_bar_gen == gen) { }
        }
        __threadfence();
    }
    __syncthreads();
}
static __device__ __forceinline__ unsigned int score_key(float s) {
    unsigned int u = __float_as_uint(s);
    return u ^ ((unsigned int)((int)u >> 31) | 0x80000000u);
}
static __device__ __forceinline__ int warp_alloc(bool pred, int* ctr) {
    unsigned int m = __ballot_sync(0xffffffffu, pred);
    int lane = threadIdx.x & 31;
    int leader = __ffs(m) - 1;
    int base = 0;
    if (m) {
        if (lane == leader) base = atomicAdd(ctr, __popc(m));
        base = __shfl_sync(0xffffffffu, base, leader);
    }
    return base + __popc(m & ((1u << lane) - 1u));
}
// merge-path partition (DESC order): first d outputs take 'a' from A
static __device__ __forceinline__ int mpath(const u64* A, int lenA,
                                            const u64* B, int lenB, int d) {
    int lo = d - lenB; if (lo < 0) lo = 0;
    int hi = d < lenA ? d : lenA;
    while (lo < hi) {
        int mid = (lo + hi) >> 1;
        if (A[mid] > B[d - 1 - mid]) lo = mid + 1; else hi = mid;
    }
    return lo;
}
static __device__ __forceinline__ void merge_chunk(const u64* A, int lenA,
                                                   const u64* B, int lenB,
                                                   u64* out, int d) {
    int a = mpath(A, lenA, B, lenB, d);
    int bi = d - a;
#pragma unroll
    for (int r = 0; r < 8; ++r) {
        bool takeA = (a < lenA) && ((bi >= lenB) || (A[a] > B[bi]));
        out[d + r] = takeA ? A[a++] : B[bi++];
    }
}
static __device__ __forceinline__ void decode_box(int b, int rank, u64 v,
                                                  const float* __restrict__ bbox,
                                                  const float* __restrict__ anchors) {
    unsigned int a = ~(unsigned int)(v & 0xffffffffULL);
    size_t s4 = (((size_t)b << 17) + a) * 4;
    float d0 = bbox[s4 + 0] * 0.1f;
    float d1 = bbox[s4 + 1] * 0.1f;
    float d2 = bbox[s4 + 2] * 0.2f;
    float d3 = bbox[s4 + 3] * 0.2f;
    float a0 = anchors[s4 + 0], a1 = anchors[s4 + 1];
    float a2 = anchors[s4 + 2], a3 = anchors[s4 + 3];
    float h = a2 - a0, w = a3 - a1;
    float cy = a0 + 0.5f * h + d0 * h;
    float cx = a1 + 0.5f * w + d1 * w;
    float h2 = h * expf(d2);
    float w2 = w * expf(d3);
    float y1 = cy - 0.5f * h2;
    float x1 = cx - 0.5f * w2;
    float y2 = y1 + h2;
    float x2 = x1 + w2;
    y1 = fminf(fmaxf(y1, 0.f), 1.f);
    x1 = fminf(fmaxf(x1, 0.f), 1.f);
    y2 = fminf(fmaxf(y2, 0.f), 1.f);
    x2 = fminf(fmaxf(x2, 0.f), 1.f);
    g_boxes[b * NPRE + rank] = make_float4(y1, x1, y2, x2);
}
// warp-synchronous bitonic stages (8 elems/lane, element i = lane*8 + r)
static __device__ __forceinline__ void shfl_stage(u64 v[8], int lane, int j, int k) {
    int jm = j >> 3;
#pragma unroll
    for (int r = 0; r < 8; ++r) {
        u64 other = __shfl_xor_sync(0xffffffffu, v[r], jm);
        int i = lane * 8 + r;
        bool lower = (lane & jm) == 0;
        bool desc = ((i & k) == 0);
        bool take_max = (lower == desc);
        u64 mx = v[r] > other ? v[r] : other;
        u64 mn = v[r] > other ? other : v[r];
        v[r] = take_max ? mx : mn;
    }
}
static __device__ __forceinline__ void reg_stage(u64 v[8], int lane, int j, int k) {
#pragma unroll
    for (int a = 0; a < 8; ++a) {
        if (!(a & j)) {
            int i = lane * 8 + a;
            bool desc = ((i & k) == 0);
            u64 x = v[a], y = v[a + j];
            if (desc ? (x < y) : (x > y)) { v[a] = y; v[a + j] = x; }
        }
    }
}

// ================= the whole pipeline, one launch =================
__global__ void __launch_bounds__(NTHR, 1)
fused_kernel(const float* __restrict__ probs,
             const float* __restrict__ bbox,
             const float* __restrict__ anchors,
             float* __restrict__ out)
{
    extern __shared__ u64 dsm[];
    __shared__ int s_w[16];
    __shared__ int s_flag, s_total, s_base;
    int t = threadIdx.x;
    int blk = blockIdx.x;
    int warp = t >> 5, lane = t & 31;
    const float4* p4 = (const float4*)probs;

    // ---- P0: histogram (512 virtual blocks of 1024 float4, batch-aligned) ----
    for (int vb = blk; vb < 512; vb += NBLK) {
        int base = vb * 1024;
        int b = base >> 16;
        float4 x[4];
#pragma unroll
        for (int u = 0; u < 4; ++u) x[u] = p4[base + u * 256 + t];
        unsigned int* Hb = g_hist + (size_t)b * HBINS;
#pragma unroll
        for (int u = 0; u < 4; ++u) {
            atomicAdd(&Hb[score_key(x[u].y) >> 18], 1u);
            atomicAdd(&Hb[score_key(x[u].w) >> 18], 1u);
        }
    }
    grid_barrier();

    // ---- P1: cutoff bin (blocks 0..7), self-cleaning hist ----
    if (blk < BATCH) {
        int b = blk;
        uint4* H4 = (uint4*)(g_hist + (size_t)b * HBINS);    // 4096 uint4
        unsigned int s = 0;
        for (int u = 0; u < 16; ++u) {
            uint4 h = H4[t * 16 + u];
            s += h.x + h.y + h.z + h.w;
        }
        unsigned int ss = s;
#pragma unroll
        for (int o = 1; o < 32; o <<= 1) {
            unsigned int v = __shfl_down_sync(0xffffffffu, ss, o);
            if (lane + o < 32) ss += v;
        }
        if (lane == 0) s_w[warp] = (int)ss;
        __syncthreads();
        if (warp == 0 && lane < 8) {
            int wv = s_w[lane];
            for (int o = 1; o < 8; o <<= 1) {
                int v = __shfl_down_sync(0xffu, wv, o);
                if (lane + o < 8) wv += v;
            }
            s_w[8 + lane] = wv;                               // inclusive suffix
        }
        __syncthreads();
        unsigned int after = (warp < 7) ? (unsigned int)s_w[8 + warp + 1] : 0u;
        unsigned int S = ss + after;
        unsigned int Snext = S - s;
        if (S >= NPRE && Snext < NPRE) {
            unsigned int run = Snext;
            int cut = t * 64;
            const unsigned int* Hb = g_hist + (size_t)b * HBINS + t * 64;
            for (int k = 63; k >= 0; --k) {
                run += Hb[k];
                if (run >= NPRE) { cut = t * 64 + k; break; }
            }
            g_cutbin[b] = cut;
        }
        __syncthreads();
        uint4 z = make_uint4(0u, 0u, 0u, 0u);
        for (int u = 0; u < 16; ++u) H4[t * 16 + u] = z;
    }
    grid_barrier();

    // ---- P2: compact candidates ----
    for (int vb = blk; vb < 512; vb += NBLK) {
        int base = vb * 1024;
        int b = base >> 16;
        int cut = g_cutbin[b];
        float4 x[4];
#pragma unroll
        for (int u = 0; u < 4; ++u) x[u] = p4[base + u * 256 + t];
#pragma unroll
        for (int u = 0; u < 4; ++u) {
            int j = base + u * 256 + t;
            unsigned int k0 = score_key(x[u].y);
            unsigned int k1 = score_key(x[u].w);
            bool q0 = (int)(k0 >> 18) >= cut;
            bool q1 = (int)(k1 >> 18) >= cut;
            int pos0 = warp_alloc(q0, &g_cand_cnt[b]);
            if (q0 && pos0 < CAND_CAP) {
                unsigned int a = (unsigned int)((2 * j) & (NA - 1));
                g_cand[b * CAND_CAP + pos0] = ((u64)k0 << 32) | (u64)(~a);
            }
            int pos1 = warp_alloc(q1, &g_cand_cnt[b]);
            if (q1 && pos1 < CAND_CAP) {
                unsigned int a = (unsigned int)((2 * j + 1) & (NA - 1));
                g_cand[b * CAND_CAP + pos1] = ((u64)k1 << 32) | (u64)(~a);
            }
        }
    }
    grid_barrier();

    // ---- P3: warp-synchronous sort of 256-runs (256 warp tasks, NO syncs) ----
    {
        int gw = blk * 8 + warp;
        if (gw < 256) {
            int b = gw >> 5, run = gw & 31;
            int cnt = g_cand_cnt[b]; if (cnt > CAND_CAP) cnt = CAND_CAP;
            u64* R = g_cand + b * CAND_CAP + run * 256;
            int valid = cnt - run * 256;
            u64 v[8];
#pragma unroll
            for (int r = 0; r < 8; ++r) {
                int i = lane * 8 + r;
                v[r] = (i < valid) ? R[i] : 0ULL;
            }
            for (int k = 2; k <= 256; k <<= 1) {
                for (int j = k >> 1; j >= 8; j >>= 1) shfl_stage(v, lane, j, k);
                if (k > 4) reg_stage(v, lane, 4, k);
                if (k > 2) reg_stage(v, lane, 2, k);
                reg_stage(v, lane, 1, k);
            }
#pragma unroll
            for (int r = 0; r < 8; ++r) R[lane * 8 + r] = v[r];   // desc run
        }
    }
    grid_barrier();

    // ---- P4: merge tree capped at top-N1 + decode (blocks 0..7) ----
    if (blk < BATCH) {
        int b = blk;
        if (t == 0) g_cand_cnt[b] = 0;                     // restore invariant
        u64* cand = g_cand + b * CAND_CAP;
        u64* scr  = (u64*)g_mask + (size_t)b * NPRE * NB;  // scratch in g_mask
        u64* scr2 = scr + 8192;
        u64* ping = dsm;                                   // 4*N1
        u64* pong = dsm + 4 * N1;                          // 2*N1
        for (int c = t; c < 1024; c += NTHR) {             // L1: 16x(256,256)->512
            int m = c >> 6, d = (c & 63) * 8;
            merge_chunk(cand + 2 * m * 256, 256, cand + 2 * m * 256 + 256, 256,
                        scr + m * 512, d);
        }
        __syncthreads();
        for (int c = t; c < 1024; c += NTHR) {             // L2: 8x(512,512)->1024
            int m = c >> 7, d = (c & 127) * 8;
            merge_chunk(scr + 2 * m * 512, 512, scr + 2 * m * 512 + 512, 512,
                        scr2 + m * 1024, d);
        }
        __syncthreads();
        for (int c = t; c < 4 * (N1 / 8); c += NTHR) {     // L3: 4x(1024,1024)->cap N1
            int m = c / (N1 / 8), d = (c % (N1 / 8)) * 8;
            merge_chunk(scr2 + 2 * m * 1024, 1024, scr2 + 2 * m * 1024 + 1024, 1024,
                        ping + m * N1, d);
        }
        __syncthreads();
        for (int c = t; c < 2 * (N1 / 8); c += NTHR) {     // L4: 2x(N1,N1)->N1
            int m = c / (N1 / 8), d = (c % (N1 / 8)) * 8;
            merge_chunk(ping + 2 * m * N1, N1, ping + 2 * m * N1 + N1, N1,
                        pong + m * N1, d);
        }
        __syncthreads();
        if (t < N1 / 8) {                                   // L5: final merge + decode
            int d = t * 8;
            const u64* A = pong;
            const u64* B = pong + N1;
            int a = mpath(A, N1, B, N1, d);
            int bi = d - a;
#pragma unroll
            for (int r = 0; r < 8; ++r) {
                bool takeA = (a < N1) && ((bi >= N1) || (A[a] > B[bi]));
                u64 v = takeA ? A[a++] : B[bi++];
                decode_box(b, d + r, v, bbox, anchors);
            }
        }
    }
    grid_barrier();

    // ---- P5: edge emission over first N1 boxes (672 tile tasks) ----
    {
        float4* s_cbox = (float4*)dsm;
        float*  s_car  = (float*)(s_cbox + 64);
        const int cum[7] = {0, 24, 44, 60, 72, 80, 84};
        for (int task = blk; task < 672; task += NBLK) {
            int b = task / 84, r = task % 84;
            int rb = 0;
            while (r >= cum[rb + 1]) ++rb;                  // rb in 0..5
            int cb = 4 * rb + (r - cum[rb]);
            const float4* boxes_b = g_boxes + b * NPRE;
            int jj0 = cb * 64;
            __syncthreads();                                 // smem reuse fence
            if (t < 64) {
                float4 c = boxes_b[jj0 + t];
                s_cbox[t] = c;
                s_car[t] = (c.z - c.x) * (c.w - c.y);
            }
            __syncthreads();
            int i = rb * 256 + t;                            // always < N1
            float4 rbx = boxes_b[i];
            float ar = (rbx.z - rbx.x) * (rbx.w - rbx.y);
#pragma unroll 4
            for (int j = 0; j < 64; ++j) {
                float4 c = s_cbox[j];
                int jj = jj0 + j;
                float dy = fminf(rbx.z, c.z) - fmaxf(rbx.x, c.x);
                float dx = fminf(rbx.w, c.w) - fmaxf(rbx.y, c.y);
                bool ov = (dy > 0.f) && (dx > 0.f) && (jj > i);
                if (__any_sync(0xffffffffu, ov)) {
                    bool e = false;
                    if (ov) {
                        float inter = dy * dx;
                        float uni = fmaxf(ar + s_car[j] - inter, 1e-12f);
                        e = __fdiv_rn(inter, uni) > NMS_THR;
                    }
                    int pos = warp_alloc(e, &g_ecnt[b]);
                    if (e && pos < ECAP)
                        g_edges[b * ECAP + pos] =
                            ((unsigned int)i << 16) | (unsigned int)jj;
                }
            }
        }
    }
    grid_barrier();

    // ---- P6: sparse fixpoint NMS on prefix (blocks 0..7) ----
    if (blk < BATCH) {
        int b = blk;
        unsigned int*  s_edges = (unsigned int*)dsm;
        unsigned char* s_keep  = (unsigned char*)(s_edges + ECAP);
        unsigned char* s_supp  = s_keep + N1;
        int ec = g_ecnt[b];
        if (t == 0) g_ecnt[b] = 0;                          // restore invariant
        if (ec <= ECAP) {
            for (int i = t; i < ec; i += NTHR) s_edges[i] = g_edges[b * ECAP + i];
            for (int i = t; i < N1; i += NTHR) s_keep[i] = 1;
            __syncthreads();
            bool converged = false;
            for (int pass = 0; pass < PASSMAX; ++pass) {
                for (int i = t; i < N1; i += NTHR) s_supp[i] = 0;
                if (t == 0) s_flag = 0;
                __syncthreads();
                for (int e = t; e < ec; e += NTHR) {
                    unsigned int p = s_edges[e];
                    if (s_keep[p >> 16]) s_supp[p & 0xffffu] = 1;
                }
                __syncthreads();
                int ch = 0;
                for (int i = t; i < N1; i += NTHR) {
                    unsigned char nk = (unsigned char)(1 - s_supp[i]);
                    if (nk != s_keep[i]) { s_keep[i] = nk; ch = 1; }
                }
                if (ch) s_flag = 1;
                __syncthreads();
                if (!s_flag) { converged = true; break; }
            }
            if (t == 0) s_total = 0;
            __syncthreads();
            int cnt = 0;
            for (int i = t; i < N1; i += NTHR) {
                g_keep[b * NPRE + i] = s_keep[i];
                cnt += s_keep[i];
            }
            for (int off = 16; off > 0; off >>= 1)
                cnt += __shfl_down_sync(0xffffffffu, cnt, off);
            if (lane == 0) atomicAdd(&s_total, cnt);
            __syncthreads();
            int done = (converged && s_total >= NPROP) ? 1 : 0;
            if (t == 0) g_done[b] = done;
            if (done)
                for (int i = N1 + t; i < NPRE; i += NTHR) g_keep[b * NPRE + i] = 0;
        } else {
            if (t == 0) g_done[b] = 0;
        }
    }
    grid_barrier();

    // ---- P7a: FALLBACK uncapped merge + decode 6000 (guarded; ~never runs) ----
    if (blk < BATCH && !g_done[blk]) {
        int b = blk;
        u64* scr  = (u64*)g_mask + (size_t)b * NPRE * NB;
        u64* scr2 = scr + 8192;
        u64* scr3 = scr + 16384;
        u64* scr4 = scr + 24576;
        u64* scr5 = scr + 32768;
        for (int c = t; c < 1024; c += NTHR) {              // 4x(1024,1024)->2048
            int m = c >> 8, d = (c & 255) * 8;
            merge_chunk(scr2 + 2 * m * 1024, 1024, scr2 + 2 * m * 1024 + 1024, 1024,
                        scr3 + m * 2048, d);
        }
        __syncthreads();
        for (int c = t; c < 1024; c += NTHR) {              // 2x(2048,2048)->4096
            int m = c >> 9, d = (c & 511) * 8;
            merge_chunk(scr3 + 2 * m * 2048, 2048, scr3 + 2 * m * 2048 + 2048, 2048,
                        scr4 + m * 4096, d);
        }
        __syncthreads();
        for (int c = t; c < 750; c += NTHR) {               // (4096,4096)->6000
            merge_chunk(scr4, 4096, scr4 + 4096, 4096, scr5, c * 8);
        }
        __syncthreads();
        for (int rank = t; rank < NPRE; rank += NTHR)
            decode_box(b, rank, scr5[rank], bbox, anchors);
    }
    grid_barrier();

    // ---- P7b: FALLBACK full mask (guarded per batch) ----
    {
        float4* s_cbox = (float4*)dsm;
        float*  s_car  = (float*)(s_cbox + 64);
        for (int task = blk; task < BATCH * 24 * 94; task += NBLK) {
            int b = task / (24 * 94);
            if (g_done[b]) continue;
            int rem = task % (24 * 94);
            int rb = rem / 94, cb = rem % 94;
            int i = rb * 256 + t;
            u64* mrow = g_mask + (size_t)b * NPRE * NB;
            if (cb * 64 + 63 < rb * 256) {                  // fully below diagonal
                if (i < NPRE) mrow[(size_t)i * NB + cb] = 0ULL;
                continue;
            }
            const float4* boxes_b = g_boxes + b * NPRE;
            int jj0 = cb * 64;
            __syncthreads();
            if (t < 64) {
                int jj = jj0 + t;
                float4 c = (jj < NPRE) ? boxes_b[jj] : make_float4(4.f, 4.f, 3.f, 3.f);
                s_cbox[t] = c;
                s_car[t] = (c.z - c.x) * (c.w - c.y);
            }
            __syncthreads();
            float4 rbx = (i < NPRE) ? boxes_b[i] : make_float4(4.f, 4.f, 3.f, 3.f);
            float ar = (rbx.z - rbx.x) * (rbx.w - rbx.y);
            u64 bits = 0ULL;
#pragma unroll 4
            for (int j = 0; j < 64; ++j) {
                float4 c = s_cbox[j];
                int jj = jj0 + j;
                float dy = fminf(rbx.z, c.z) - fmaxf(rbx.x, c.x);
                float dx = fminf(rbx.w, c.w) - fmaxf(rbx.y, c.y);
                bool ov = (dy > 0.f) && (dx > 0.f) && (jj > i);
                if (__any_sync(0xffffffffu, ov)) {
                    if (ov) {
                        float inter = dy * dx;
                        float uni = fmaxf(ar + s_car[j] - inter, 1e-12f);
                        if (__fdiv_rn(inter, uni) > NMS_THR) bits |= (1ULL << j);
                    }
                }
            }
            if (i < NPRE) mrow[(size_t)i * NB + cb] = bits;
        }
    }
    grid_barrier();

    // ---- P7c: FALLBACK serial greedy scan (guarded; warp 0 of blocks 0..7) ----
    if (blk < BATCH) {
        int b = blk;
        if (!g_done[b] && warp == 0) {
            u64 r0 = 0, r1 = 0, r2 = 0;
            const u64* mrow = g_mask + (size_t)b * NPRE * NB;
            for (int i = 0; i < NPRE; ++i) {
                int wi = i >> 6;
                u64 v = (wi < 32) ? r0 : (wi < 64) ? r1 : r2;
                u64 wv = __shfl_sync(0xffffffffu, v, wi & 31);
                int supp = (int)((wv >> (i & 63)) & 1ULL);
                if (!supp) {
                    const u64* row = mrow + (size_t)i * NB;
                    r0 |= __ldcg(row + lane);
                    r1 |= __ldcg(row + lane + 32);
                    if (lane < 30) r2 |= __ldcg(row + lane + 64);
                }
                if (lane == 0) g_keep[b * NPRE + i] = (unsigned char)(supp ^ 1);
            }
        }
    }
    grid_barrier();

    // ---- P8: compact kept boxes -> output (blocks 0..7) ----
    if (blk < BATCH) {
        int b = blk;
        for (int k = t; k < NPROP * 4; k += NTHR) out[b * NPROP * 4 + k] = 0.f;
        if (t == 0) s_base = 0;
        __syncthreads();
        for (int tile = 0; tile < 24; ++tile) {
            int i = tile * 256 + t;
            int kp = (i < NPRE) ? (int)g_keep[b * NPRE + i] : 0;
            unsigned int m = __ballot_sync(0xffffffffu, kp);
            if (lane == 0) s_w[warp] = __popc(m);
            __syncthreads();
            int base = s_base;
            if (warp == 0 && lane < 8) {
                int wv = s_w[lane];
                for (int o = 1; o < 8; o <<= 1) {
                    int u = __shfl_up_sync(0xffu, wv, o);
                    if (lane >= o) wv += u;
                }
                s_w[lane] = wv;                              // inclusive prefix
            }
            __syncthreads();
            int prev = (warp == 0) ? 0 : s_w[warp - 1];
            int rank = base + prev + __popc(m & ((1u << lane) - 1u));
            if (kp && rank < NPROP)
                ((float4*)out)[b * NPROP + rank] = g_boxes[b * NPRE + i];
            __syncthreads();
            if (t == 0) s_base = base + s_w[7];
            __syncthreads();
        }
    }
}

// ---------------- launch ----------------
extern "C" void kernel_launch(void* const* d_in, const int* in_sizes, int n_in,
                              void* d_out, int out_size) {
    const float* probs   = (const float*)d_in[0];
    const float* bbox    = (const float*)d_in[1];
    const float* anchors = (const float*)d_in[2];
    float* out = (float*)d_out;

    cudaFuncSetAttribute(fused_kernel,
                         cudaFuncAttributeMaxDynamicSharedMemorySize, SMEM_BYTES);
    fused_kernel<<<NBLK, NTHR, SMEM_BYTES>>>(probs, bbox, anchors, out);
}

// round 10
// speedup vs baseline: 1.3376x; 1.3376x over previous
#include <cuda_runtime.h>
#include <cstdint>
#include <math.h>

#define BATCH 8
#define NA 131072            // anchors per batch (2^17)
#define NPRE 6000            // PRE_NMS_LIMIT
#define NB 94                // ceil(NPRE/64)  (fallback mask)
#define NPROP 1000
#define CAND_CAP 8192
#define HBINS 16384          // key >> 18
#define NMS_THR 0.7f
#define N1 1536              // fast-path prefix rows
#define ECAP 6144            // edge list capacity per batch
#define PASSMAX 64

typedef unsigned long long u64;

// ---------------- device scratch (static, no allocation) ----------------
// Invariants: g_hist all-zero, g_cand_cnt/g_ecnt zero at entry of each launch
// (zero-init at load; each consumer kernel re-zeroes after use).
__device__ unsigned int  g_hist[BATCH * HBINS];
__device__ int           g_cutbin[BATCH];
__device__ int           g_cand_cnt[BATCH];
__device__ u64           g_cand[BATCH * CAND_CAP];
__device__ float4        g_boxes[BATCH * NPRE];
__device__ int           g_ecnt[BATCH];
__device__ unsigned int  g_edges[BATCH * ECAP];
__device__ u64           g_mask[(size_t)BATCH * NPRE * NB];   // + merge scratch
__device__ unsigned char g_keep[BATCH * NPRE];
__device__ int           g_done[BATCH];

// ---------------- helpers ----------------
static __device__ __forceinline__ void cp_async8(unsigned int smem, const void* g) {
    asm volatile("cp.async.ca.shared.global [%0], [%1], 8;" :: "r"(smem), "l"(g) : "memory");
}
static __device__ __forceinline__ void cp_commit() {
    asm volatile("cp.async.commit_group;" ::: "memory");
}
static __device__ __forceinline__ void cp_wait15() {
    asm volatile("cp.async.wait_group 15;" ::: "memory");
}
static __device__ __forceinline__ unsigned int score_key(float s) {
    unsigned int u = __float_as_uint(s);
    return u ^ ((unsigned int)((int)u >> 31) | 0x80000000u);
}
static __device__ __forceinline__ int warp_alloc(bool pred, int* ctr) {
    unsigned int m = __ballot_sync(0xffffffffu, pred);
    int lane = threadIdx.x & 31;
    int leader = __ffs(m) - 1;
    int base = 0;
    if (m) {
        if (lane == leader) base = atomicAdd(ctr, __popc(m));
        base = __shfl_sync(0xffffffffu, base, leader);
    }
    return base + __popc(m & ((1u << lane) - 1u));
}
// merge-path partition (DESC order): of first d outputs, how many come from A
static __device__ __forceinline__ int mpath(const u64* A, int lenA,
                                            const u64* B, int lenB, int d) {
    int lo = d - lenB; if (lo < 0) lo = 0;
    int hi = d < lenA ? d : lenA;
    while (lo < hi) {
        int mid = (lo + hi) >> 1;
        if (A[mid] > B[d - 1 - mid]) lo = mid + 1; else hi = mid;
    }
    return lo;
}
static __device__ __forceinline__ void merge_chunk(const u64* A, int lenA,
                                                   const u64* B, int lenB,
                                                   u64* out, int d) {
    int a = mpath(A, lenA, B, lenB, d);
    int bi = d - a;
#pragma unroll
    for (int r = 0; r < 8; ++r) {
        bool takeA = (a < lenA) && ((bi >= lenB) || (A[a] > B[bi]));
        out[d + r] = takeA ? A[a++] : B[bi++];
    }
}
static __device__ __forceinline__ void decode_box(int b, int rank, u64 v,
                                                  const float* __restrict__ bbox,
                                                  const float* __restrict__ anchors) {
    unsigned int a = ~(unsigned int)(v & 0xffffffffULL);
    size_t s4 = (((size_t)b << 17) + a) * 4;
    float d0 = bbox[s4 + 0] * 0.1f;
    float d1 = bbox[s4 + 1] * 0.1f;
    float d2 = bbox[s4 + 2] * 0.2f;
    float d3 = bbox[s4 + 3] * 0.2f;
    float a0 = anchors[s4 + 0], a1 = anchors[s4 + 1];
    float a2 = anchors[s4 + 2], a3 = anchors[s4 + 3];
    float h = a2 - a0, w = a3 - a1;
    float cy = a0 + 0.5f * h + d0 * h;
    float cx = a1 + 0.5f * w + d1 * w;
    float h2 = h * expf(d2);
    float w2 = w * expf(d3);
    float y1 = cy - 0.5f * h2;
    float x1 = cx - 0.5f * w2;
    float y2 = y1 + h2;
    float x2 = x1 + w2;
    y1 = fminf(fmaxf(y1, 0.f), 1.f);
    x1 = fminf(fmaxf(x1, 0.f), 1.f);
    y2 = fminf(fmaxf(y2, 0.f), 1.f);
    x2 = fminf(fmaxf(x2, 0.f), 1.f);
    g_boxes[b * NPRE + rank] = make_float4(y1, x1, y2, x2);
}

// ---------------- 1: histogram ----------------
__global__ void hist_kernel(const float* __restrict__ probs) {
    const float4* p4 = (const float4*)probs;
    int t = threadIdx.x;
    int base = blockIdx.x * 1024;
    int b = base >> 16;
    float4 x[4];
#pragma unroll
    for (int u = 0; u < 4; ++u) x[u] = p4[base + u * 256 + t];
    unsigned int* Hb = g_hist + (size_t)b * HBINS;
#pragma unroll
    for (int u = 0; u < 4; ++u) {
        atomicAdd(&Hb[score_key(x[u].y) >> 18], 1u);
        atomicAdd(&Hb[score_key(x[u].w) >> 18], 1u);
    }
}

// ---------------- 2: cutoff bin (self-cleaning hist) ----------------
__global__ void cutoff_kernel() {
    int b = blockIdx.x, t = threadIdx.x;
    __shared__ unsigned int wtot[32];
    __shared__ unsigned int wsuf[32];
    uint4* H4 = (uint4*)(g_hist + (size_t)b * HBINS);
    int warp = t >> 5, lane = t & 31;
    uint4 h[4];
#pragma unroll
    for (int u = 0; u < 4; ++u) h[u] = H4[t * 4 + u];
    uint4 z = make_uint4(0u, 0u, 0u, 0u);
#pragma unroll
    for (int u = 0; u < 4; ++u) H4[t * 4 + u] = z;
    unsigned int s = 0;
#pragma unroll
    for (int u = 0; u < 4; ++u) s += h[u].x + h[u].y + h[u].z + h[u].w;
    unsigned int ss = s;
#pragma unroll
    for (int o = 1; o < 32; o <<= 1) {
        unsigned int v = __shfl_down_sync(0xffffffffu, ss, o);
        if (lane + o < 32) ss += v;
    }
    if (lane == 0) wtot[warp] = ss;
    __syncthreads();
    if (warp == 0) {
        unsigned int wv = wtot[lane];
#pragma unroll
        for (int o = 1; o < 32; o <<= 1) {
            unsigned int v = __shfl_down_sync(0xffffffffu, wv, o);
            if (lane + o < 32) wv += v;
        }
        wsuf[lane] = wv;
    }
    __syncthreads();
    unsigned int after_warp = (warp < 31) ? wsuf[warp + 1] : 0u;
    unsigned int S = ss + after_warp;
    unsigned int Snext = S - s;
    if (S >= NPRE && Snext < NPRE) {
        unsigned int bins[16];
#pragma unroll
        for (int u = 0; u < 4; ++u) {
            bins[u * 4 + 0] = h[u].x; bins[u * 4 + 1] = h[u].y;
            bins[u * 4 + 2] = h[u].z; bins[u * 4 + 3] = h[u].w;
        }
        unsigned int run = Snext;
        int cut = t * 16;
        for (int k = 15; k >= 0; --k) {
            run += bins[k];
            if (run >= NPRE) { cut = t * 16 + k; break; }
        }
        g_cutbin[b] = cut;
    }
}

// ---------------- 3: compact candidates ----------------
__global__ void compact_kernel(const float* __restrict__ probs) {
    const float4* p4 = (const float4*)probs;
    int t = threadIdx.x;
    int base = blockIdx.x * 1024;
    int b = base >> 16;
    int cut = g_cutbin[b];
    float4 x[4];
#pragma unroll
    for (int u = 0; u < 4; ++u) x[u] = p4[base + u * 256 + t];
#pragma unroll
    for (int u = 0; u < 4; ++u) {
        int j = base + u * 256 + t;
        unsigned int k0 = score_key(x[u].y);
        unsigned int k1 = score_key(x[u].w);
        bool p0 = (int)(k0 >> 18) >= cut;
        bool p1 = (int)(k1 >> 18) >= cut;
        int pos0 = warp_alloc(p0, &g_cand_cnt[b]);
        if (p0 && pos0 < CAND_CAP) {
            unsigned int a = (unsigned int)((2 * j) & (NA - 1));
            g_cand[b * CAND_CAP + pos0] = ((u64)k0 << 32) | (u64)(~a);
        }
        int pos1 = warp_alloc(p1, &g_cand_cnt[b]);
        if (p1 && pos1 < CAND_CAP) {
            unsigned int a = (unsigned int)((2 * j + 1) & (NA - 1));
            g_cand[b * CAND_CAP + pos1] = ((u64)k1 << 32) | (u64)(~a);
        }
    }
}

// ---------------- warp-synchronous bitonic (8 elems/lane, i = lane*8 + r) ----------------
static __device__ __forceinline__ void shfl_stage(u64 v[8], int lane, int j, int k) {
    int jm = j >> 3;
#pragma unroll
    for (int r = 0; r < 8; ++r) {
        u64 other = __shfl_xor_sync(0xffffffffu, v[r], jm);
        int i = lane * 8 + r;
        bool lower = (lane & jm) == 0;
        bool desc = ((i & k) == 0);
        bool take_max = (lower == desc);
        u64 mx = v[r] > other ? v[r] : other;
        u64 mn = v[r] > other ? other : v[r];
        v[r] = take_max ? mx : mn;
    }
}
static __device__ __forceinline__ void reg_stage(u64 v[8], int lane, int j, int k) {
#pragma unroll
    for (int a = 0; a < 8; ++a) {
        if (!(a & j)) {
            int i = lane * 8 + a;
            bool desc = ((i & k) == 0);
            u64 x = v[a], y = v[a + j];
            if (desc ? (x < y) : (x > y)) { v[a] = y; v[a + j] = x; }
        }
    }
}

// ---------------- 4a: warp-synchronous sort of 256-runs (32 blocks x 256 thr) ----------------
// 256 warp tasks total: batch b, run 0..31; NO __syncthreads, NO smem.
__global__ void warp_sort_kernel() {
    int lane = threadIdx.x & 31;
    int gw = blockIdx.x * 8 + (threadIdx.x >> 5);
    int b = gw >> 5, run = gw & 31;
    int cnt = g_cand_cnt[b]; if (cnt > CAND_CAP) cnt = CAND_CAP;
    u64* R = g_cand + b * CAND_CAP + run * 256;
    int valid = cnt - run * 256;
    u64 v[8];
#pragma unroll
    for (int r = 0; r < 8; ++r) {
        int i = lane * 8 + r;
        v[r] = (i < valid) ? R[i] : 0ULL;
    }
    for (int k = 2; k <= 256; k <<= 1) {
        for (int j = k >> 1; j >= 8; j >>= 1) shfl_stage(v, lane, j, k);
        if (k > 4) reg_stage(v, lane, 4, k);
        if (k > 2) reg_stage(v, lane, 2, k);
        reg_stage(v, lane, 1, k);
    }
#pragma unroll
    for (int r = 0; r < 8; ++r) R[lane * 8 + r] = v[r];      // descending run
}

// ---------------- 4b: merge tree capped at top-N1 + decode (8 blocks, 256 thr) ----------------
// L1/L2 via gmem scratch (carved from g_mask), L3..L5 in dynamic smem.
__global__ void fast_merge_decode_kernel(const float* __restrict__ bbox,
                                         const float* __restrict__ anchors) {
    extern __shared__ u64 dsm[];                    // ping 4*N1 + pong 2*N1
    int b = blockIdx.x, t = threadIdx.x;
    if (t == 0) g_cand_cnt[b] = 0;                  // restore invariant
    u64* cand = g_cand + b * CAND_CAP;
    u64* scr  = (u64*)g_mask + (size_t)b * NPRE * NB;
    u64* scr2 = scr + 8192;
    u64* ping = dsm;
    u64* pong = dsm + 4 * N1;
    for (int c = t; c < 1024; c += 256) {           // L1: 16x(256,256)->512
        int m = c >> 6, d = (c & 63) * 8;
        merge_chunk(cand + 2 * m * 256, 256, cand + 2 * m * 256 + 256, 256,
                    scr + m * 512, d);
    }
    __syncthreads();
    for (int c = t; c < 1024; c += 256) {           // L2: 8x(512,512)->1024
        int m = c >> 7, d = (c & 127) * 8;
        merge_chunk(scr + 2 * m * 512, 512, scr + 2 * m * 512 + 512, 512,
                    scr2 + m * 1024, d);
    }
    __syncthreads();
    for (int c = t; c < 4 * (N1 / 8); c += 256) {   // L3: 4x(1024,1024)->cap N1
        int m = c / (N1 / 8), d = (c % (N1 / 8)) * 8;
        merge_chunk(scr2 + 2 * m * 1024, 1024, scr2 + 2 * m * 1024 + 1024, 1024,
                    ping + m * N1, d);
    }
    __syncthreads();
    for (int c = t; c < 2 * (N1 / 8); c += 256) {   // L4: 2x(N1,N1)->cap N1
        int m = c / (N1 / 8), d = (c % (N1 / 8)) * 8;
        merge_chunk(ping + 2 * m * N1, N1, ping + 2 * m * N1 + N1, N1,
                    pong + m * N1, d);
    }
    __syncthreads();
    if (t < N1 / 8) {                               // L5: final merge + decode [0,N1)
        int d = t * 8;
        const u64* A = pong;
        const u64* B = pong + N1;
        int a = mpath(A, N1, B, N1, d);
        int bi = d - a;
#pragma unroll
        for (int r = 0; r < 8; ++r) {
            bool takeA = (a < N1) && ((bi >= N1) || (A[a] > B[bi]));
            u64 v = takeA ? A[a++] : B[bi++];
            decode_box(b, d + r, v, bbox, anchors);
        }
    }
}

// ---------------- 5a: edge emission over first N1 boxes ----------------
__global__ void edge_kernel() {
    int rowblk = blockIdx.x, colblk = blockIdx.y, b = blockIdx.z;
    if (colblk < 2 * rowblk) return;
    int t = threadIdx.x;
    int i0 = rowblk * 128 + t;
    int i1 = i0 + 64;
    __shared__ float4 s_box[64];
    __shared__ float  s_area[64];
    int jj0 = colblk * 64;
    const float4* boxes_b = g_boxes + b * NPRE;
    {
        float4 c = boxes_b[jj0 + t];
        s_box[t] = c;
        s_area[t] = (c.z - c.x) * (c.w - c.y);
    }
    __syncthreads();
    float4 rb0 = boxes_b[i0];
    float4 rb1 = boxes_b[i1];
    float ar0 = (rb0.z - rb0.x) * (rb0.w - rb0.y);
    float ar1 = (rb1.z - rb1.x) * (rb1.w - rb1.y);
#pragma unroll 4
    for (int j = 0; j < 64; ++j) {
        float4 c = s_box[j];
        float ca = s_area[j];
        int jj = jj0 + j;
        float dy0 = fminf(rb0.z, c.z) - fmaxf(rb0.x, c.x);
        float dx0 = fminf(rb0.w, c.w) - fmaxf(rb0.y, c.y);
        float dy1 = fminf(rb1.z, c.z) - fmaxf(rb1.x, c.x);
        float dx1 = fminf(rb1.w, c.w) - fmaxf(rb1.y, c.y);
        bool ov0 = (dy0 > 0.f) && (dx0 > 0.f) && (jj > i0);
        bool ov1 = (dy1 > 0.f) && (dx1 > 0.f) && (jj > i1);
        if (__any_sync(0xffffffffu, ov0 || ov1)) {
            bool e0 = false, e1 = false;
            if (ov0) {
                float inter = dy0 * dx0;
                float uni = fmaxf(ar0 + ca - inter, 1e-12f);
                e0 = __fdiv_rn(inter, uni) > NMS_THR;
            }
            if (ov1) {
                float inter = dy1 * dx1;
                float uni = fmaxf(ar1 + ca - inter, 1e-12f);
                e1 = __fdiv_rn(inter, uni) > NMS_THR;
            }
            int pos0 = warp_alloc(e0, &g_ecnt[b]);
            if (e0 && pos0 < ECAP)
                g_edges[b * ECAP + pos0] = ((unsigned int)i0 << 16) | (unsigned int)jj;
            int pos1 = warp_alloc(e1, &g_ecnt[b]);
            if (e1 && pos1 < ECAP)
                g_edges[b * ECAP + pos1] = ((unsigned int)i1 << 16) | (unsigned int)jj;
        }
    }
}

// ---------------- 6a: sparse fixpoint NMS on prefix (1 block / batch) ----------------
__global__ void fixpoint_kernel() {
    int b = blockIdx.x, t = threadIdx.x;            // 256 threads
    __shared__ unsigned int  s_edges[ECAP];
    __shared__ unsigned char s_keep[N1];
    __shared__ unsigned char s_supp[N1];
    __shared__ int s_changed;
    __shared__ int s_total;
    int ec = g_ecnt[b];
    if (t == 0) g_ecnt[b] = 0;
    if (ec > ECAP) { if (t == 0) g_done[b] = 0; return; }
    for (int i = t; i < ec; i += 256) s_edges[i] = g_edges[b * ECAP + i];
    for (int i = t; i < N1; i += 256) s_keep[i] = 1;
    __syncthreads();
    bool converged = false;
    for (int pass = 0; pass < PASSMAX; ++pass) {
        for (int i = t; i < N1; i += 256) s_supp[i] = 0;
        if (t == 0) s_changed = 0;
        __syncthreads();
        for (int e = t; e < ec; e += 256) {
            unsigned int p = s_edges[e];
            if (s_keep[p >> 16]) s_supp[p & 0xffffu] = 1;
        }
        __syncthreads();
        int ch = 0;
        for (int i = t; i < N1; i += 256) {
            unsigned char nk = (unsigned char)(1 - s_supp[i]);
            if (nk != s_keep[i]) { s_keep[i] = nk; ch = 1; }
        }
        if (ch) s_changed = 1;
        __syncthreads();
        if (!s_changed) { converged = true; break; }
    }
    if (t == 0) s_total = 0;
    __syncthreads();
    int cnt = 0;
    for (int i = t; i < N1; i += 256) {
        g_keep[b * NPRE + i] = s_keep[i];
        cnt += s_keep[i];
    }
    for (int off = 16; off > 0; off >>= 1) cnt += __shfl_down_sync(0xffffffffu, cnt, off);
    if ((t & 31) == 0) atomicAdd(&s_total, cnt);
    __syncthreads();
    int done = (converged && s_total >= NPROP) ? 1 : 0;
    if (t == 0) g_done[b] = done;
    if (done)
        for (int i = N1 + t; i < NPRE; i += 256) g_keep[b * NPRE + i] = 0;
}

// ---------------- 4c: FALLBACK uncapped merge + decode 6000 (guarded) ----------------
// Continues from L2 scratch (8 runs of 1024, valid because 4b ran unconditionally).
__global__ void full_merge_decode_kernel(const float* __restrict__ bbox,
                                         const float* __restrict__ anchors) {
    int b = blockIdx.x, t = threadIdx.x;            // 256 threads
    if (g_done[b]) return;
    u64* scr  = (u64*)g_mask + (size_t)b * NPRE * NB;
    u64* scr2 = scr + 8192;
    u64* scr3 = scr + 16384;
    u64* scr4 = scr + 24576;
    u64* scr5 = scr + 32768;
    for (int c = t; c < 1024; c += 256) {           // 4x(1024,1024)->2048
        int m = c >> 8, d = (c & 255) * 8;
        merge_chunk(scr2 + 2 * m * 1024, 1024, scr2 + 2 * m * 1024 + 1024, 1024,
                    scr3 + m * 2048, d);
    }
    __syncthreads();
    for (int c = t; c < 1024; c += 256) {           // 2x(2048,2048)->4096
        int m = c >> 9, d = (c & 511) * 8;
        merge_chunk(scr3 + 2 * m * 2048, 2048, scr3 + 2 * m * 2048 + 2048, 2048,
                    scr4 + m * 4096, d);
    }
    __syncthreads();
    for (int c = t; c < 750; c += 256)              // (4096,4096)->top 6000
        merge_chunk(scr4, 4096, scr4 + 4096, 4096, scr5, c * 8);
    __syncthreads();
    for (int rank = t; rank < NPRE; rank += 256)
        decode_box(b, rank, scr5[rank], bbox, anchors);
}

// ---------------- 5b: fallback full mask (persistent, guarded) ----------------
#define RB 47
#define CB 94
__global__ void mask_fb_kernel() {
    int t = threadIdx.x;
    const int T = BATCH * RB * CB;
    for (int tile = blockIdx.x; tile < T; tile += gridDim.x) {
        int b = tile / (RB * CB);
        if (g_done[b]) continue;
        int rb_ = (tile / CB) % RB;
        int cb_ = tile % CB;
        int i0 = rb_ * 128 + t;
        int i1 = i0 + 64;
        u64* mrow = g_mask + (size_t)b * NPRE * NB;
        if (cb_ < 2 * rb_) {
            if (i0 < NPRE) mrow[(size_t)i0 * NB + cb_] = 0ULL;
            if (i1 < NPRE) mrow[(size_t)i1 * NB + cb_] = 0ULL;
            continue;
        }
        __shared__ float4 s_box[64];
        __shared__ float  s_area[64];
        int jj0 = cb_ * 64;
        const float4* boxes_b = g_boxes + b * NPRE;
        {
            int jj = jj0 + t;
            float4 c = (jj < NPRE) ? boxes_b[jj] : make_float4(4.f, 4.f, 3.f, 3.f);
            s_box[t] = c;
            s_area[t] = (c.z - c.x) * (c.w - c.y);
        }
        __syncthreads();
        float4 rb0 = (i0 < NPRE) ? boxes_b[i0] : make_float4(4.f, 4.f, 3.f, 3.f);
        float4 rb1 = (i1 < NPRE) ? boxes_b[i1] : make_float4(4.f, 4.f, 3.f, 3.f);
        float ar0 = (rb0.z - rb0.x) * (rb0.w - rb0.y);
        float ar1 = (rb1.z - rb1.x) * (rb1.w - rb1.y);
        u64 bits0 = 0ULL, bits1 = 0ULL;
#pragma unroll 4
        for (int j = 0; j < 64; ++j) {
            float4 c = s_box[j];
            float ca = s_area[j];
            int jj = jj0 + j;
            float dy0 = fminf(rb0.z, c.z) - fmaxf(rb0.x, c.x);
            float dx0 = fminf(rb0.w, c.w) - fmaxf(rb0.y, c.y);
            float dy1 = fminf(rb1.z, c.z) - fmaxf(rb1.x, c.x);
            float dx1 = fminf(rb1.w, c.w) - fmaxf(rb1.y, c.y);
            bool ov0 = (dy0 > 0.f) && (dx0 > 0.f) && (jj > i0);
            bool ov1 = (dy1 > 0.f) && (dx1 > 0.f) && (jj > i1);
            if (__any_sync(0xffffffffu, ov0 || ov1)) {
                if (ov0) {
                    float inter = dy0 * dx0;
                    float uni = fmaxf(ar0 + ca - inter, 1e-12f);
                    if (__fdiv_rn(inter, uni) > NMS_THR) bits0 |= (1ULL << j);
                }
                if (ov1) {
                    float inter = dy1 * dx1;
                    float uni = fmaxf(ar1 + ca - inter, 1e-12f);
                    if (__fdiv_rn(inter, uni) > NMS_THR) bits1 |= (1ULL << j);
                }
            }
        }
        if (i0 < NPRE) mrow[(size_t)i0 * NB + cb_] = bits0;
        if (i1 < NPRE) mrow[(size_t)i1 * NB + cb_] = bits1;
        __syncthreads();
    }
}

// ---------------- 6b: fallback full scan (guarded) ----------------
__global__ void nms_scan_kernel() {
    int b = blockIdx.x, t = threadIdx.x;            // 32 threads
    if (g_done[b]) return;
    __shared__ u64 ring[16 * 96];
    for (int k = t; k < 16 * 96; k += 32) ring[k] = 0ULL;
    __syncwarp();
    u64 r0 = 0, r1 = 0, r2 = 0;
    unsigned int sbase = (unsigned int)__cvta_generic_to_shared(ring);
    const u64* mrow = g_mask + (size_t)b * NPRE * NB;
    for (int r = 0; r < 16; ++r) {
        const u64* src = mrow + (size_t)r * NB;
        unsigned int dst = sbase + (unsigned int)((r * 96 + t) * 8);
        cp_async8(dst, src + t);
        cp_async8(dst + 32 * 8, src + t + 32);
        if (t < 30) cp_async8(dst + 64 * 8, src + t + 64);
        cp_commit();
    }
    for (int i = 0; i < NPRE; ++i) {
        cp_wait15();
        int wi = i >> 6;
        u64 v = (wi < 32) ? r0 : (wi < 64) ? r1 : r2;
        u64 wv = __shfl_sync(0xffffffffu, v, wi & 31);
        int supp = (int)((wv >> (i & 63)) & 1ULL);
        int slot = i & 15;
        if (!supp) {
            r0 |= ring[slot * 96 + t];
            r1 |= ring[slot * 96 + t + 32];
            r2 |= ring[slot * 96 + t + 64];
        }
        if (t == 0) g_keep[b * NPRE + i] = (unsigned char)(supp ^ 1);
        int r = i + 16;
        if (r < NPRE) {
            const u64* src = mrow + (size_t)r * NB;
            unsigned int dst = sbase + (unsigned int)(((r & 15) * 96 + t) * 8);
            cp_async8(dst, src + t);
            cp_async8(dst + 32 * 8, src + t + 32);
            if (t < 30) cp_async8(dst + 64 * 8, src + t + 64);
        }
        cp_commit();
    }
}

// ---------------- 7: compact kept boxes -> output (ballot scan) ----------------
__global__ void final_kernel(float* __restrict__ out) {
    int b = blockIdx.x, t = threadIdx.x;            // 1024 threads
    for (int k = t; k < NPROP * 4; k += 1024) out[b * NPROP * 4 + k] = 0.f;
    __shared__ int wsum[32];
    __shared__ int s_base;
    if (t == 0) s_base = 0;
    int warp = t >> 5, lane = t & 31;
    __syncthreads();
    for (int tile = 0; tile < 6; ++tile) {
        int i = tile * 1024 + t;
        int kp = (i < NPRE) ? (int)g_keep[b * NPRE + i] : 0;
        unsigned int m = __ballot_sync(0xffffffffu, kp);
        if (lane == 0) wsum[warp] = __popc(m);
        __syncthreads();
        int base = s_base;
        if (warp == 0) {
            int wv = wsum[lane];
#pragma unroll
            for (int o = 1; o < 32; o <<= 1) {
                int u = __shfl_up_sync(0xffffffffu, wv, o);
                if (lane >= o) wv += u;
            }
            wsum[lane] = wv;
        }
        __syncthreads();
        int prev = (warp == 0) ? 0 : wsum[warp - 1];
        int rank = base + prev + __popc(m & ((1u << lane) - 1u));
        if (kp && rank < NPROP)
            ((float4*)out)[b * NPROP + rank] = g_boxes[b * NPRE + i];
        __syncthreads();
        if (t == 0) s_base = base + wsum[31];
        __syncthreads();
    }
}

// ---------------- launch ----------------
extern "C" void kernel_launch(void* const* d_in, const int* in_sizes, int n_in,
                              void* d_out, int out_size) {
    const float* probs   = (const float*)d_in[0];
    const float* bbox    = (const float*)d_in[1];
    const float* anchors = (const float*)d_in[2];
    float* out = (float*)d_out;

    hist_kernel<<<512, 256>>>(probs);
    cutoff_kernel<<<BATCH, 1024>>>();
    compact_kernel<<<512, 256>>>(probs);
    warp_sort_kernel<<<32, 256>>>();
    cudaFuncSetAttribute(fast_merge_decode_kernel,
                         cudaFuncAttributeMaxDynamicSharedMemorySize, 6 * N1 * 8);
    fast_merge_decode_kernel<<<BATCH, 256, 6 * N1 * 8>>>(bbox, anchors);
    edge_kernel<<<dim3(12, 24, BATCH), 64>>>();
    fixpoint_kernel<<<BATCH, 256>>>();
    full_merge_decode_kernel<<<BATCH, 256>>>(bbox, anchors);   // no-op when done
    mask_fb_kernel<<<296, 64>>>();                              // near no-op when done
    nms_scan_kernel<<<BATCH, 32>>>();                           // no-op when done
    final_kernel<<<BATCH, 1024>>>(out);
}

// round 11
// speedup vs baseline: 1.8464x; 1.3804x over previous
#include <cuda_runtime.h>
#include <cstdint>
#include <math.h>

#define BATCH 8
#define NA 131072            // anchors per batch (2^17)
#define NPRE 6000            // PRE_NMS_LIMIT
#define NPROP 1000
#define CAND_CAP 8192
#define HBINS 16384          // key >> 18
#define NMS_THR 0.7f
#define N1 1536              // fast-path prefix rows
#define ECAP 6144            // edge list capacity per batch
#define PASSMAX 64

typedef unsigned long long u64;

// ---------------- device scratch (static, no allocation) ----------------
// Invariants: g_hist all-zero, g_cand_cnt/g_ecnt zero at entry of each launch
// (zero-init at load; each consumer kernel re-zeroes after use).
__device__ unsigned int  g_hist[BATCH * HBINS];
__device__ int           g_cutbin[BATCH];
__device__ int           g_cand_cnt[BATCH];
__device__ u64           g_cand[BATCH * CAND_CAP];
__device__ float4        g_boxes[BATCH * NPRE];
__device__ int           g_ecnt[BATCH];
__device__ unsigned int  g_edges[BATCH * ECAP];
__device__ int           g_done[BATCH];

// ---------------- helpers ----------------
static __device__ __forceinline__ unsigned int score_key(float s) {
    unsigned int u = __float_as_uint(s);
    return u ^ ((unsigned int)((int)u >> 31) | 0x80000000u);
}
static __device__ __forceinline__ int warp_alloc(bool pred, int* ctr) {
    unsigned int m = __ballot_sync(0xffffffffu, pred);
    int lane = threadIdx.x & 31;
    int leader = __ffs(m) - 1;
    int base = 0;
    if (m) {
        if (lane == leader) base = atomicAdd(ctr, __popc(m));
        base = __shfl_sync(0xffffffffu, base, leader);
    }
    return base + __popc(m & ((1u << lane) - 1u));
}
// merge-path partition (DESC order): of first d outputs, how many come from A
static __device__ __forceinline__ int mpath(const u64* A, int lenA,
                                            const u64* B, int lenB, int d) {
    int lo = d - lenB; if (lo < 0) lo = 0;
    int hi = d < lenA ? d : lenA;
    while (lo < hi) {
        int mid = (lo + hi) >> 1;
        if (A[mid] > B[d - 1 - mid]) lo = mid + 1; else hi = mid;
    }
    return lo;
}
static __device__ __forceinline__ void merge_chunk(const u64* A, int lenA,
                                                   const u64* B, int lenB,
                                                   u64* out, int d) {
    int a = mpath(A, lenA, B, lenB, d);
    int bi = d - a;
#pragma unroll
    for (int r = 0; r < 8; ++r) {
        bool takeA = (a < lenA) && ((bi >= lenB) || (A[a] > B[bi]));
        out[d + r] = takeA ? A[a++] : B[bi++];
    }
}
static __device__ __forceinline__ void decode_box(int b, int rank, u64 v,
                                                  const float* __restrict__ bbox,
                                                  const float* __restrict__ anchors) {
    unsigned int a = ~(unsigned int)(v & 0xffffffffULL);
    size_t s4 = (((size_t)b << 17) + a) * 4;
    float d0 = bbox[s4 + 0] * 0.1f;
    float d1 = bbox[s4 + 1] * 0.1f;
    float d2 = bbox[s4 + 2] * 0.2f;
    float d3 = bbox[s4 + 3] * 0.2f;
    float a0 = anchors[s4 + 0], a1 = anchors[s4 + 1];
    float a2 = anchors[s4 + 2], a3 = anchors[s4 + 3];
    float h = a2 - a0, w = a3 - a1;
    float cy = a0 + 0.5f * h + d0 * h;
    float cx = a1 + 0.5f * w + d1 * w;
    float h2 = h * expf(d2);
    float w2 = w * expf(d3);
    float y1 = cy - 0.5f * h2;
    float x1 = cx - 0.5f * w2;
    float y2 = y1 + h2;
    float x2 = x1 + w2;
    y1 = fminf(fmaxf(y1, 0.f), 1.f);
    x1 = fminf(fmaxf(x1, 0.f), 1.f);
    y2 = fminf(fmaxf(y2, 0.f), 1.f);
    x2 = fminf(fmaxf(x2, 0.f), 1.f);
    g_boxes[b * NPRE + rank] = make_float4(y1, x1, y2, x2);
}

// ---------------- 1: histogram ----------------
__global__ void hist_kernel(const float* __restrict__ probs) {
    const float4* p4 = (const float4*)probs;
    int t = threadIdx.x;
    int base = blockIdx.x * 1024;
    int b = base >> 16;
    float4 x[4];
#pragma unroll
    for (int u = 0; u < 4; ++u) x[u] = p4[base + u * 256 + t];
    unsigned int* Hb = g_hist + (size_t)b * HBINS;
#pragma unroll
    for (int u = 0; u < 4; ++u) {
        atomicAdd(&Hb[score_key(x[u].y) >> 18], 1u);
        atomicAdd(&Hb[score_key(x[u].w) >> 18], 1u);
    }
}

// ---------------- 2: cutoff bin (self-cleaning hist) ----------------
__global__ void cutoff_kernel() {
    int b = blockIdx.x, t = threadIdx.x;            // 1024 threads
    __shared__ unsigned int wtot[32];
    __shared__ unsigned int wsuf[32];
    uint4* H4 = (uint4*)(g_hist + (size_t)b * HBINS);
    int warp = t >> 5, lane = t & 31;
    uint4 h[4];
#pragma unroll
    for (int u = 0; u < 4; ++u) h[u] = H4[t * 4 + u];
    uint4 z = make_uint4(0u, 0u, 0u, 0u);
#pragma unroll
    for (int u = 0; u < 4; ++u) H4[t * 4 + u] = z;
    unsigned int s = 0;
#pragma unroll
    for (int u = 0; u < 4; ++u) s += h[u].x + h[u].y + h[u].z + h[u].w;
    unsigned int ss = s;
#pragma unroll
    for (int o = 1; o < 32; o <<= 1) {
        unsigned int v = __shfl_down_sync(0xffffffffu, ss, o);
        if (lane + o < 32) ss += v;
    }
    if (lane == 0) wtot[warp] = ss;
    __syncthreads();
    if (warp == 0) {
        unsigned int wv = wtot[lane];
#pragma unroll
        for (int o = 1; o < 32; o <<= 1) {
            unsigned int v = __shfl_down_sync(0xffffffffu, wv, o);
            if (lane + o < 32) wv += v;
        }
        wsuf[lane] = wv;
    }
    __syncthreads();
    unsigned int after_warp = (warp < 31) ? wsuf[warp + 1] : 0u;
    unsigned int S = ss + after_warp;
    unsigned int Snext = S - s;
    if (S >= NPRE && Snext < NPRE) {
        unsigned int bins[16];
#pragma unroll
        for (int u = 0; u < 4; ++u) {
            bins[u * 4 + 0] = h[u].x; bins[u * 4 + 1] = h[u].y;
            bins[u * 4 + 2] = h[u].z; bins[u * 4 + 3] = h[u].w;
        }
        unsigned int run = Snext;
        int cut = t * 16;
        for (int k = 15; k >= 0; --k) {
            run += bins[k];
            if (run >= NPRE) { cut = t * 16 + k; break; }
        }
        g_cutbin[b] = cut;
    }
}

// ---------------- 3: compact candidates ----------------
__global__ void compact_kernel(const float* __restrict__ probs) {
    const float4* p4 = (const float4*)probs;
    int t = threadIdx.x;
    int base = blockIdx.x * 1024;
    int b = base >> 16;
    int cut = g_cutbin[b];
    float4 x[4];
#pragma unroll
    for (int u = 0; u < 4; ++u) x[u] = p4[base + u * 256 + t];
#pragma unroll
    for (int u = 0; u < 4; ++u) {
        int j = base + u * 256 + t;
        unsigned int k0 = score_key(x[u].y);
        unsigned int k1 = score_key(x[u].w);
        bool p0 = (int)(k0 >> 18) >= cut;
        bool p1 = (int)(k1 >> 18) >= cut;
        int pos0 = warp_alloc(p0, &g_cand_cnt[b]);
        if (p0 && pos0 < CAND_CAP) {
            unsigned int a = (unsigned int)((2 * j) & (NA - 1));
            g_cand[b * CAND_CAP + pos0] = ((u64)k0 << 32) | (u64)(~a);
        }
        int pos1 = warp_alloc(p1, &g_cand_cnt[b]);
        if (p1 && pos1 < CAND_CAP) {
            unsigned int a = (unsigned int)((2 * j + 1) & (NA - 1));
            g_cand[b * CAND_CAP + pos1] = ((u64)k1 << 32) | (u64)(~a);
        }
    }
}

// ---------------- warp-synchronous bitonic (8 elems/lane, i = lane*8 + r) ----------------
static __device__ __forceinline__ void shfl_stage(u64 v[8], int lane, int j, int k) {
    int jm = j >> 3;
#pragma unroll
    for (int r = 0; r < 8; ++r) {
        u64 other = __shfl_xor_sync(0xffffffffu, v[r], jm);
        int i = lane * 8 + r;
        bool lower = (lane & jm) == 0;
        bool desc = ((i & k) == 0);
        bool take_max = (lower == desc);
        u64 mx = v[r] > other ? v[r] : other;
        u64 mn = v[r] > other ? other : v[r];
        v[r] = take_max ? mx : mn;
    }
}
static __device__ __forceinline__ void reg_stage(u64 v[8], int lane, int j, int k) {
#pragma unroll
    for (int a = 0; a < 8; ++a) {
        if (!(a & j)) {
            int i = lane * 8 + a;
            bool desc = ((i & k) == 0);
            u64 x = v[a], y = v[a + j];
            if (desc ? (x < y) : (x > y)) { v[a] = y; v[a + j] = x; }
        }
    }
}

// ---------------- 4a: warp sort 256-runs + smem merge to 2048-runs ----------------
// 32 blocks x 256 thr: block = (batch, quarter). 8 warps sort 256 each (no sync),
// then 3 smem merge-path levels -> one 2048 descending run in gmem.
__global__ void sort2048_kernel() {
    __shared__ u64 ping[2048];
    __shared__ u64 pong[2048];
    int t = threadIdx.x;
    int lane = t & 31, warp = t >> 5;
    int b = blockIdx.x >> 2, q = blockIdx.x & 3;
    int cnt = g_cand_cnt[b]; if (cnt > CAND_CAP) cnt = CAND_CAP;
    u64* R = g_cand + b * CAND_CAP + q * 2048;
    int valid = cnt - q * 2048 - warp * 256;        // for this warp's 256-segment
    u64 v[8];
#pragma unroll
    for (int r = 0; r < 8; ++r) {
        int i = lane * 8 + r;
        v[r] = (i < valid) ? R[warp * 256 + i] : 0ULL;
    }
    for (int k = 2; k <= 256; k <<= 1) {
        for (int j = k >> 1; j >= 8; j >>= 1) shfl_stage(v, lane, j, k);
        if (k > 4) reg_stage(v, lane, 4, k);
        if (k > 2) reg_stage(v, lane, 2, k);
        reg_stage(v, lane, 1, k);
    }
#pragma unroll
    for (int r = 0; r < 8; ++r) ping[warp * 256 + lane * 8 + r] = v[r];
    __syncthreads();
    // L1: 4 x (256,256) -> 512 ; chunk per thread
    {
        int m = t >> 6, d = (t & 63) * 8;
        merge_chunk(ping + 2 * m * 256, 256, ping + 2 * m * 256 + 256, 256,
                    pong + m * 512, d);
    }
    __syncthreads();
    // L2: 2 x (512,512) -> 1024
    {
        int m = t >> 7, d = (t & 127) * 8;
        merge_chunk(pong + 2 * m * 512, 512, pong + 2 * m * 512 + 512, 512,
                    ping + m * 1024, d);
    }
    __syncthreads();
    // L3: (1024,1024) -> 2048
    merge_chunk(ping, 1024, ping + 1024, 1024, pong, t * 8);
    __syncthreads();
    for (int i = t; i < 2048; i += 256) R[i] = pong[i];
}

// ---------------- 4b: smem-resident top-N1 merge + decode (8 blocks, 256 thr) ----------------
__global__ void fast_merge_decode_kernel(const float* __restrict__ bbox,
                                         const float* __restrict__ anchors) {
    extern __shared__ u64 dsm[];                    // S[8192] + P[2*N1]
    u64* S = dsm;
    u64* P = dsm + CAND_CAP;
    int b = blockIdx.x, t = threadIdx.x;
    if (t == 0) g_cand_cnt[b] = 0;                  // restore invariant
    const u64* cand = g_cand + b * CAND_CAP;
    for (int i = t; i < CAND_CAP; i += 256) S[i] = cand[i];
    __syncthreads();
    // L1: 2 merges (2048,2048) capped at N1
    for (int c = t; c < 2 * (N1 / 8); c += 256) {
        int m = c / (N1 / 8), d = (c % (N1 / 8)) * 8;
        merge_chunk(S + m * 4096, 2048, S + m * 4096 + 2048, 2048, P + m * N1, d);
    }
    __syncthreads();
    // L2: final (N1,N1) capped at N1 + decode
    if (t < N1 / 8) {
        int d = t * 8;
        const u64* A = P;
        const u64* B = P + N1;
        int a = mpath(A, N1, B, N1, d);
        int bi = d - a;
#pragma unroll
        for (int r = 0; r < 8; ++r) {
            bool takeA = (a < N1) && ((bi >= N1) || (A[a] > B[bi]));
            u64 v = takeA ? A[a++] : B[bi++];
            decode_box(b, d + r, v, bbox, anchors);
        }
    }
}

// ---------------- 5: edge emission over first N1 boxes ----------------
__global__ void edge_kernel() {
    int rowblk = blockIdx.x, colblk = blockIdx.y, b = blockIdx.z;
    if (colblk < 2 * rowblk) return;
    int t = threadIdx.x;
    int i0 = rowblk * 128 + t;
    int i1 = i0 + 64;
    __shared__ float4 s_box[64];
    __shared__ float  s_area[64];
    int jj0 = colblk * 64;
    const float4* boxes_b = g_boxes + b * NPRE;
    {
        float4 c = boxes_b[jj0 + t];
        s_box[t] = c;
        s_area[t] = (c.z - c.x) * (c.w - c.y);
    }
    __syncthreads();
    float4 rb0 = boxes_b[i0];
    float4 rb1 = boxes_b[i1];
    float ar0 = (rb0.z - rb0.x) * (rb0.w - rb0.y);
    float ar1 = (rb1.z - rb1.x) * (rb1.w - rb1.y);
#pragma unroll 4
    for (int j = 0; j < 64; ++j) {
        float4 c = s_box[j];
        float ca = s_area[j];
        int jj = jj0 + j;
        float dy0 = fminf(rb0.z, c.z) - fmaxf(rb0.x, c.x);
        float dx0 = fminf(rb0.w, c.w) - fmaxf(rb0.y, c.y);
        float dy1 = fminf(rb1.z, c.z) - fmaxf(rb1.x, c.x);
        float dx1 = fminf(rb1.w, c.w) - fmaxf(rb1.y, c.y);
        bool ov0 = (dy0 > 0.f) && (dx0 > 0.f) && (jj > i0);
        bool ov1 = (dy1 > 0.f) && (dx1 > 0.f) && (jj > i1);
        if (__any_sync(0xffffffffu, ov0 || ov1)) {
            bool e0 = false, e1 = false;
            if (ov0) {
                float inter = dy0 * dx0;
                float uni = fmaxf(ar0 + ca - inter, 1e-12f);
                e0 = __fdiv_rn(inter, uni) > NMS_THR;
            }
            if (ov1) {
                float inter = dy1 * dx1;
                float uni = fmaxf(ar1 + ca - inter, 1e-12f);
                e1 = __fdiv_rn(inter, uni) > NMS_THR;
            }
            int pos0 = warp_alloc(e0, &g_ecnt[b]);
            if (e0 && pos0 < ECAP)
                g_edges[b * ECAP + pos0] = ((unsigned int)i0 << 16) | (unsigned int)jj;
            int pos1 = warp_alloc(e1, &g_ecnt[b]);
            if (e1 && pos1 < ECAP)
                g_edges[b * ECAP + pos1] = ((unsigned int)i1 << 16) | (unsigned int)jj;
        }
    }
}

// ---------------- 6: fixpoint NMS on prefix + fused output write ----------------
__global__ void fixpoint_out_kernel(float* __restrict__ out) {
    int b = blockIdx.x, t = threadIdx.x;            // 256 threads
    int warp = t >> 5, lane = t & 31;
    __shared__ unsigned int  s_edges[ECAP];
    __shared__ unsigned char s_keep[N1];
    __shared__ unsigned char s_supp[N1];
    __shared__ int s_flag, s_total, s_base;
    __shared__ int s_w[8];
    int ec = g_ecnt[b];
    if (t == 0) g_ecnt[b] = 0;                      // restore invariant
    if (ec > ECAP) { if (t == 0) g_done[b] = 0; return; }
    for (int i = t; i < ec; i += 256) s_edges[i] = g_edges[b * ECAP + i];
    for (int i = t; i < N1; i += 256) s_keep[i] = 1;
    __syncthreads();
    bool converged = false;
    for (int pass = 0; pass < PASSMAX; ++pass) {
        for (int i = t; i < N1; i += 256) s_supp[i] = 0;
        if (t == 0) s_flag = 0;
        __syncthreads();
        for (int e = t; e < ec; e += 256) {
            unsigned int p = s_edges[e];
            if (s_keep[p >> 16]) s_supp[p & 0xffffu] = 1;
        }
        __syncthreads();
        int ch = 0;
        for (int i = t; i < N1; i += 256) {
            unsigned char nk = (unsigned char)(1 - s_supp[i]);
            if (nk != s_keep[i]) { s_keep[i] = nk; ch = 1; }
        }
        if (ch) s_flag = 1;
        __syncthreads();
        if (!s_flag) { converged = true; break; }
    }
    if (t == 0) s_total = 0;
    __syncthreads();
    int cnt = 0;
    for (int i = t; i < N1; i += 256) cnt += s_keep[i];
    for (int off = 16; off > 0; off >>= 1) cnt += __shfl_down_sync(0xffffffffu, cnt, off);
    if (lane == 0) atomicAdd(&s_total, cnt);
    __syncthreads();
    int done = (converged && s_total >= NPROP) ? 1 : 0;
    if (t == 0) { g_done[b] = done; s_base = 0; }
    __syncthreads();
    if (!done) return;                              // fallback kernel writes output
    // fused compaction: first NPROP kept prefix boxes -> out (zeros tail N/A: kept>=NPROP)
    for (int k = t; k < NPROP * 4; k += 256) out[b * NPROP * 4 + k] = 0.f;
    __syncthreads();
    for (int tile = 0; tile < N1 / 256; ++tile) {
        int i = tile * 256 + t;
        int kp = (int)s_keep[i];
        unsigned int m = __ballot_sync(0xffffffffu, kp);
        if (lane == 0) s_w[warp] = __popc(m);
        __syncthreads();
        int base = s_base;
        if (warp == 0 && lane < 8) {
            int wv = s_w[lane];
            for (int o = 1; o < 8; o <<= 1) {
                int u = __shfl_up_sync(0xffu, wv, o);
                if (lane >= o) wv += u;
            }
            s_w[lane] = wv;                          // inclusive
        }
        __syncthreads();
        int prev = (warp == 0) ? 0 : s_w[warp - 1];
        int rank = base + prev + __popc(m & ((1u << lane) - 1u));
        if (kp && rank < NPROP)
            ((float4*)out)[b * NPROP + rank] = g_boxes[b * NPRE + i];
        __syncthreads();
        if (t == 0) s_base = base + s_w[7];
        __syncthreads();
    }
}

// ---------------- 7: FALLBACK all-in-one (guarded; ~never runs) ----------------
// One block per batch: full smem merge -> decode 6000 -> sequential greedy NMS
// -> compact output. Exact reference semantics; only used when prefix fails.
__global__ void fallback_kernel(const float* __restrict__ bbox,
                                const float* __restrict__ anchors,
                                float* __restrict__ out) {
    int b = blockIdx.x, t = threadIdx.x;            // 256 threads
    if (g_done[b]) return;
    extern __shared__ u64 fsm[];                    // A[8192] + B[8192] + supp
    u64* A = fsm;
    u64* B = fsm + CAND_CAP;
    unsigned char* supp = (unsigned char*)(fsm + 2 * CAND_CAP);
    int warp = t >> 5, lane = t & 31;
    __shared__ int s_w[8];
    __shared__ int s_base;
    const u64* cand = g_cand + b * CAND_CAP;
    for (int i = t; i < CAND_CAP; i += 256) A[i] = cand[i];
    __syncthreads();
    // L1: 2 x (2048,2048) -> 4096 (uncapped)
    for (int c = t; c < 1024; c += 256) {
        int m = c >> 9, d = (c & 511) * 8;
        merge_chunk(A + m * 4096, 2048, A + m * 4096 + 2048, 2048, B + m * 4096, d);
    }
    __syncthreads();
    // L2: (4096,4096) -> top 6000 into A
    for (int c = t; c < NPRE / 8; c += 256)
        merge_chunk(B, 4096, B + 4096, 4096, A, c * 8);
    __syncthreads();
    for (int rank = t; rank < NPRE; rank += 256)
        decode_box(b, rank, A[rank], bbox, anchors);
    for (int i = t; i < NPRE; i += 256) supp[i] = 0;
    __syncthreads();
    // sequential greedy NMS (exact reference order)
    const float4* boxes_b = g_boxes + b * NPRE;
    for (int i = 0; i < NPRE; ++i) {
        if (!supp[i]) {
            float4 bi_ = boxes_b[i];
            float ai = (bi_.z - bi_.x) * (bi_.w - bi_.y);
            for (int j = i + 1 + t; j < NPRE; j += 256) {
                if (supp[j]) continue;
                float4 c = boxes_b[j];
                float dy = fminf(bi_.z, c.z) - fmaxf(bi_.x, c.x);
                float dx = fminf(bi_.w, c.w) - fmaxf(bi_.y, c.y);
                if (dy > 0.f && dx > 0.f) {
                    float inter = dy * dx;
                    float ca = (c.z - c.x) * (c.w - c.y);
                    float uni = fmaxf(ai + ca - inter, 1e-12f);
                    if (__fdiv_rn(inter, uni) > NMS_THR) supp[j] = 1;
                }
            }
        }
        __syncthreads();
    }
    // compact output
    for (int k = t; k < NPROP * 4; k += 256) out[b * NPROP * 4 + k] = 0.f;
    if (t == 0) s_base = 0;
    __syncthreads();
    for (int tile = 0; tile < 24; ++tile) {
        int i = tile * 256 + t;
        int kp = (i < NPRE) ? (int)(1 - supp[i]) : 0;
        unsigned int m = __ballot_sync(0xffffffffu, kp);
        if (lane == 0) s_w[warp] = __popc(m);
        __syncthreads();
        int base = s_base;
        if (warp == 0 && lane < 8) {
            int wv = s_w[lane];
            for (int o = 1; o < 8; o <<= 1) {
                int u = __shfl_up_sync(0xffu, wv, o);
                if (lane >= o) wv += u;
            }
            s_w[lane] = wv;
        }
        __syncthreads();
        int prev = (warp == 0) ? 0 : s_w[warp - 1];
        int rank = base + prev + __popc(m & ((1u << lane) - 1u));
        if (kp && rank < NPROP)
            ((float4*)out)[b * NPROP + rank] = boxes_b[i];
        __syncthreads();
        if (t == 0) s_base = base + s_w[7];
        __syncthreads();
    }
}

// ---------------- launch ----------------
extern "C" void kernel_launch(void* const* d_in, const int* in_sizes, int n_in,
                              void* d_out, int out_size) {
    const float* probs   = (const float*)d_in[0];
    const float* bbox    = (const float*)d_in[1];
    const float* anchors = (const float*)d_in[2];
    float* out = (float*)d_out;

    const int fm_smem = (CAND_CAP + 2 * N1) * 8;              // 90112 B
    const int fb_smem = 2 * CAND_CAP * 8 + NPRE + 64;         // ~137 KB
    cudaFuncSetAttribute(fast_merge_decode_kernel,
                         cudaFuncAttributeMaxDynamicSharedMemorySize, fm_smem);
    cudaFuncSetAttribute(fallback_kernel,
                         cudaFuncAttributeMaxDynamicSharedMemorySize, fb_smem);

    hist_kernel<<<512, 256>>>(probs);
    cutoff_kernel<<<BATCH, 1024>>>();
    compact_kernel<<<512, 256>>>(probs);
    sort2048_kernel<<<32, 256>>>();
    fast_merge_decode_kernel<<<BATCH, 256, fm_smem>>>(bbox, anchors);
    edge_kernel<<<dim3(12, 24, BATCH), 64>>>();
    fixpoint_out_kernel<<<BATCH, 256>>>(out);
    fallback_kernel<<<BATCH, 256, fb_smem>>>(bbox, anchors, out);  // no-op when done
}